// round 1
// baseline (speedup 1.0000x reference)
#include <cuda_runtime.h>
#include <math.h>

// Problem constants
#define NG   8          // graphs
#define LN   1024       // nodes per graph
#define NH   8          // heads
#define HD   16         // head dim
#define DS   64         // d_state
#define NNODE (NG*LN)   // 8192
#define NEDGE 131072    // NG * LN * AVG_DEG
#define BH   (NG*NH)    // 64 batched matrices
#define MSZ  (1024ULL*1024ULL)   // elements per 1024x1024 matrix

// ---------------- scratch (allocation-free: __device__ globals) ----------------
__device__ float g_A [BH*MSZ];   // "last" / ping
__device__ float g_T [BH*MSZ];   // tmp / pong (also reused as AT scatter target)
__device__ float g_O [BH*MSZ];   // "out" ping
__device__ float g_O2[BH*MSZ];   // "out" pong (final result lives here)
__device__ float g_G [NG*MSZ];   // G[b,l,t] = C_d @ B_d^T
__device__ float g_s0[NH*NNODE];
__device__ float g_s1[NH*NNODE];
__device__ float g_denom[BH*LN];   // rowsum + dummy + TOL
__device__ float g_dtself[BH*LN];

// ---------------- small prep kernels ----------------
__device__ __forceinline__ float softplus_f(float z) {
    return (z > 20.f) ? z : log1pf(expf(z));
}

__global__ void coef_kernel(const float* __restrict__ dt, const float* __restrict__ dt_bias) {
    int n = blockIdx.x * 256 + threadIdx.x;
    if (n >= NNODE) return;
    int b = n >> 10, l = n & 1023;
    #pragma unroll
    for (int h = 0; h < NH; h++) {
        float bias = dt_bias[h];
        const float* p = dt + (size_t)n * (NH * 4) + h * 4;
        float a0 = -softplus_f(p[0] + bias);
        float a1 = -softplus_f(p[1] + bias);
        float a2 = -softplus_f(p[2] + bias);
        g_s0[h * NNODE + n] = expf(0.5f * a0);
        g_s1[h * NNODE + n] = expf(0.5f * a1);
        g_denom[(b * NH + h) * LN + l] = expf(a2) + 0.1f;   // dummy + TOL folded in
        g_dtself[(b * NH + h) * LN + l] = p[3];
    }
}

__global__ void zero_kernel(float4* __restrict__ p) {
    size_t i = (size_t)blockIdx.x * 256 + threadIdx.x;
    p[i] = make_float4(0.f, 0.f, 0.f, 0.f);
}

// scatter edges into transposed matrix AT[b,h,dl,sl] (stored in g_T) + row norms
__global__ void scatter_kernel(const int* __restrict__ src, const int* __restrict__ dst) {
    int e = blockIdx.x * 128 + threadIdx.x;
    if (e >= NEDGE) return;
    int s = src[e], d = dst[e];
    int b = s >> 10, sl = s & 1023, dl = d & 1023;
    #pragma unroll
    for (int h = 0; h < NH; h++) {
        float attr = g_s0[h * NNODE + s] * g_s1[h * NNODE + d];
        size_t base = ((size_t)(b * NH + h) * LN + dl) * LN + sl;  // transposed layout
        atomicAdd(&g_T[base], attr);
        atomicAdd(&g_denom[(b * NH + h) * LN + sl], attr);
    }
}

// M[bh,i,j] = AT[bh,i,j] / denom[bh,j];  last = M; out = M + I
__global__ void build_m_kernel() {
    size_t idx = (size_t)blockIdx.x * 256 + threadIdx.x;   // 64M threads
    int j = (int)(idx & 1023);
    size_t r = idx >> 10;            // bh*1024 + i
    int bh = (int)(r >> 10);
    int i  = (int)(r & 1023);
    float v = g_T[idx] / g_denom[bh * LN + j];
    g_A[idx] = v;
    g_O[idx] = v + ((i == j) ? 1.f : 0.f);
}

// ---------------- batched SGEMM: C = A@B (+A) , all 1024^3, z = batch ----------------
#define BM 128
#define BN 128
#define BK 16
#define TM 8
#define TN 8

template <bool ADD_A>
__global__ void __launch_bounds__(256)
sgemm_kernel(const float* __restrict__ A, const float* __restrict__ B, float* __restrict__ C) {
    const int K = 1024, N = 1024;
    size_t off = (size_t)blockIdx.z * MSZ;
    A += off; B += off; C += off;

    __shared__ float As[BK][BM + 1];   // transposed store, padded
    __shared__ float Bs[BK][BN];

    const int tid  = threadIdx.x;
    const int aRow = tid >> 2;          // 0..63
    const int aCol = (tid & 3) << 2;    // 0,4,8,12
    const int bRow = tid >> 5;          // 0..7
    const int bCol = (tid & 31) << 2;   // 0..124
    const int tRow = (tid >> 4) * TM;   // 0..120
    const int tCol = (tid & 15) * TN;   // 0..120

    const float* Aptr = A + (size_t)(blockIdx.y * BM) * K;
    const float* Bptr = B + blockIdx.x * BN;

    float acc[TM][TN] = {};
    float regM[TM], regN[TN];

    for (int k0 = 0; k0 < K; k0 += BK) {
        #pragma unroll
        for (int s = 0; s < 2; s++) {
            int r = aRow + s * 64;
            float4 v = *(const float4*)(Aptr + (size_t)r * K + k0 + aCol);
            As[aCol + 0][r] = v.x; As[aCol + 1][r] = v.y;
            As[aCol + 2][r] = v.z; As[aCol + 3][r] = v.w;
        }
        #pragma unroll
        for (int s = 0; s < 2; s++) {
            int r = bRow + s * 8;
            *(float4*)(&Bs[r][bCol]) = *(const float4*)(Bptr + (size_t)(k0 + r) * N + bCol);
        }
        __syncthreads();
        #pragma unroll
        for (int k = 0; k < BK; k++) {
            #pragma unroll
            for (int i = 0; i < TM; i++) regM[i] = As[k][tRow + i];
            #pragma unroll
            for (int j = 0; j < TN; j++) regN[j] = Bs[k][tCol + j];
            #pragma unroll
            for (int i = 0; i < TM; i++)
                #pragma unroll
                for (int j = 0; j < TN; j++)
                    acc[i][j] += regM[i] * regN[j];
        }
        __syncthreads();
    }

    #pragma unroll
    for (int i = 0; i < TM; i++) {
        size_t row = (size_t)blockIdx.y * BM + tRow + i;
        float* Crow = C + row * N + blockIdx.x * BN + tCol;
        const float* Arow = A + row * K + blockIdx.x * BN + tCol; // K==N square
        #pragma unroll
        for (int j = 0; j < TN; j += 4) {
            float4 v;
            v.x = acc[i][j]; v.y = acc[i][j+1]; v.z = acc[i][j+2]; v.w = acc[i][j+3];
            if (ADD_A) {
                float4 a = *(const float4*)(Arow + j);
                v.x += a.x; v.y += a.y; v.z += a.z; v.w += a.w;
            }
            *(float4*)(Crow + j) = v;
        }
    }
}

// ---------------- G[b,l,t] = sum_d C[b,l,d]*B[b,t,d] ----------------
__global__ void gram_kernel(const float* __restrict__ Bm, const float* __restrict__ Cm) {
    int b = blockIdx.z;
    __shared__ float Cs[16][65];
    __shared__ float Bs[16][65];
    int tid = threadIdx.y * 16 + threadIdx.x;
    for (int i = tid; i < 16 * 64; i += 256) {
        int r = i >> 6, d = i & 63;
        Cs[r][d] = Cm[((size_t)b * LN + blockIdx.y * 16 + r) * DS + d];
        Bs[r][d] = Bm[((size_t)b * LN + blockIdx.x * 16 + r) * DS + d];
    }
    __syncthreads();
    float acc = 0.f;
    #pragma unroll
    for (int d = 0; d < DS; d++) acc += Cs[threadIdx.y][d] * Bs[threadIdx.x][d];
    int row = blockIdx.y * 16 + threadIdx.y;
    int col = blockIdx.x * 16 + threadIdx.x;
    g_G[((size_t)b * LN + row) * LN + col] = acc;
}

// ---------------- final: y[b,h,l,e] = sum_t out*ds[t]*G[l,t]*x[t,e] + D[h]*x[l,e] ----------------
__global__ void final_kernel(const float* __restrict__ x, const float* __restrict__ D,
                             float* __restrict__ out) {
    int l = blockIdx.x, h = blockIdx.y, b = blockIdx.z;
    int tid = threadIdx.x;
    size_t bh = (size_t)(b * NH + h);
    const float* Lrow = g_O2 + ((bh << 10) + l) * 1024;
    const float* ds   = g_dtself + (bh << 10);
    const float* Grow = g_G + (((size_t)b << 10) + l) * 1024;

    float acc[HD];
    #pragma unroll
    for (int e = 0; e < HD; e++) acc[e] = 0.f;

    for (int t = tid; t < LN; t += 128) {
        float w = Lrow[t] * ds[t] * Grow[t];
        const float4* xp = (const float4*)(x + (((size_t)(b << 10) + t) << 7) + h * HD);
        #pragma unroll
        for (int q = 0; q < 4; q++) {
            float4 v = xp[q];
            acc[q*4+0] += w * v.x; acc[q*4+1] += w * v.y;
            acc[q*4+2] += w * v.z; acc[q*4+3] += w * v.w;
        }
    }
    #pragma unroll
    for (int e = 0; e < HD; e++) {
        #pragma unroll
        for (int o = 16; o > 0; o >>= 1)
            acc[e] += __shfl_down_sync(0xffffffffu, acc[e], o);
    }
    __shared__ float red[4][HD];
    int warp = tid >> 5, lane = tid & 31;
    if (lane == 0) {
        #pragma unroll
        for (int e = 0; e < HD; e++) red[warp][e] = acc[e];
    }
    __syncthreads();
    if (tid < HD) {
        float s = red[0][tid] + red[1][tid] + red[2][tid] + red[3][tid];
        size_t node = ((size_t)b << 10) + l;
        float xv = x[(node << 7) + h * HD + tid];
        // output channel layout: c = e*NH + h  (from transpose(0,2,3,1))
        out[(node << 7) + tid * NH + h] = s + D[h] * xv;
    }
}

// ---------------- launch ----------------
extern "C" void kernel_launch(void* const* d_in, const int* in_sizes, int n_in,
                              void* d_out, int out_size) {
    const float* x       = (const float*)d_in[0];
    const float* Bm      = (const float*)d_in[1];
    const float* Cm      = (const float*)d_in[2];
    const float* dt      = (const float*)d_in[3];
    const float* dt_bias = (const float*)d_in[4];
    const float* Dv      = (const float*)d_in[5];
    const int*   edges   = (const int*)d_in[6];
    float* out = (float*)d_out;

    float *pA, *pT, *pO, *pO2;
    cudaGetSymbolAddress((void**)&pA,  g_A);
    cudaGetSymbolAddress((void**)&pT,  g_T);
    cudaGetSymbolAddress((void**)&pO,  g_O);
    cudaGetSymbolAddress((void**)&pO2, g_O2);

    coef_kernel<<<(NNODE + 255) / 256, 256>>>(dt, dt_bias);
    zero_kernel<<<(int)(BH * MSZ / 4 / 256), 256>>>((float4*)pT);
    scatter_kernel<<<NEDGE / 128, 128>>>(edges, edges + NEDGE);
    build_m_kernel<<<(int)(BH * MSZ / 256), 256>>>();

    dim3 gg(8, 8, BH);
    // doubling chain: last=A in pA, out=I+A in pO
    sgemm_kernel<false><<<gg, 256>>>(pA, pA, pT);    // A^2
    sgemm_kernel<true ><<<gg, 256>>>(pO, pT, pO2);   // out @ (I+A^2)
    sgemm_kernel<false><<<gg, 256>>>(pT, pT, pA);    // A^4
    sgemm_kernel<true ><<<gg, 256>>>(pO2, pA, pO);
    sgemm_kernel<false><<<gg, 256>>>(pA, pA, pT);    // A^8
    sgemm_kernel<true ><<<gg, 256>>>(pO, pT, pO2);
    sgemm_kernel<false><<<gg, 256>>>(pT, pT, pA);    // A^16
    sgemm_kernel<true ><<<gg, 256>>>(pO2, pA, pO);
    sgemm_kernel<false><<<gg, 256>>>(pA, pA, pT);    // A^32
    sgemm_kernel<true ><<<gg, 256>>>(pO, pT, pO2);   // final out -> g_O2

    gram_kernel<<<dim3(64, 64, NG), dim3(16, 16)>>>(Bm, Cm);
    final_kernel<<<dim3(LN, NH, NG), 128>>>(x, Dv, out);
}